// round 17
// baseline (speedup 1.0000x reference)
#include <cuda_runtime.h>
#include <cstdint>

#define BB 8
#define SSL 1024
#define HH 8
#define DDIM 96
#define NKEY 7

__constant__ int c_dim[7]  = {1, 1, 2, 2, 2, 2, 2};
__constant__ int c_foff[7] = {0, 8, 16, 32, 48, 64, 80};
__constant__ int c_roff[7] = {0, 1, 2, 4, 6, 8, 10};

__device__ float g_Q[BB * HH * SSL * DDIM];
__device__ float g_K[BB * HH * SSL * DDIM];
__device__ float g_V[BB * HH * SSL * DDIM];
__device__ float g_O[BB * HH * SSL * DDIM];
__device__ float g_Wt[NKEY * 3 * 4096];   // pre-rounded tf32 QKV weights

__device__ __forceinline__ float tf32r(float x) {
    uint32_t u;
    asm("cvt.rna.tf32.f32 %0, %1;" : "=r"(u) : "f"(x));
    return __uint_as_float(u);
}

__device__ __forceinline__ void mma_tf32(float* c, const uint32_t* a,
                                         uint32_t b0, uint32_t b1) {
    asm volatile(
        "mma.sync.aligned.m16n8k8.row.col.f32.tf32.tf32.f32 "
        "{%0,%1,%2,%3}, {%4,%5,%6,%7}, {%8,%9}, {%0,%1,%2,%3};"
        : "+f"(c[0]), "+f"(c[1]), "+f"(c[2]), "+f"(c[3])
        : "r"(a[0]), "r"(a[1]), "r"(a[2]), "r"(a[3]), "r"(b0), "r"(b1));
}

__device__ __forceinline__ void ldsm_x4(uint32_t& r0, uint32_t& r1,
                                        uint32_t& r2, uint32_t& r3, uint32_t addr) {
    asm volatile("ldmatrix.sync.aligned.m8n8.x4.shared.b16 {%0,%1,%2,%3}, [%4];"
        : "=r"(r0), "=r"(r1), "=r"(r2), "=r"(r3) : "r"(addr));
}

__device__ __forceinline__ uint32_t s2u(const void* p) {
    return (uint32_t)__cvta_generic_to_shared(p);
}
__device__ __forceinline__ void cp_async16(uint32_t saddr, const void* g) {
    asm volatile("cp.async.cg.shared.global [%0], [%1], 16;" :: "r"(saddr), "l"(g));
}
#define CP_COMMIT() asm volatile("cp.async.commit_group;")

// ---------------------------------------------------------------------------
// Kernel 0: pre-round QKV weights into g_Wt (tf32 values, [key*3+m3][4096])
// ---------------------------------------------------------------------------
__global__ __launch_bounds__(256) void k_prew(
    const float* __restrict__ Wq, const float* __restrict__ Wk,
    const float* __restrict__ Wv)
{
    const int z   = blockIdx.x;        // 0..20
    const int key = z / 3, m3 = z % 3;
    const float* src = ((m3 == 0) ? Wq : (m3 == 1) ? Wk : Wv) + key * 4096;
    float* dst = g_Wt + z * 4096;
    for (int i = threadIdx.x; i < 4096; i += 256)
        dst[i] = tf32r(src[i]);
}

// ---------------------------------------------------------------------------
// Kernel 1: FUSED QKV projection + head split, tf32 MMA
// W fragments LDG'd from g_Wt (L1-resident); smem = x tile only (~35 KB)
// grid (S/64, B, 7) -> 4 blocks/SM
// ---------------------------------------------------------------------------
#define XPITCH 68
#define PROJ_SMEM_FLOATS (128 * XPITCH)

__global__ __launch_bounds__(256) void k_proj(
    const float* __restrict__ x0, const float* __restrict__ x1,
    const float* __restrict__ x2, const float* __restrict__ x3,
    const float* __restrict__ x4, const float* __restrict__ x5,
    const float* __restrict__ x6)
{
    extern __shared__ float sm[];
    float* xs = sm;   // [rows][68]

    const int key = blockIdx.z;
    const int b   = blockIdx.y;
    const int s0  = blockIdx.x * 64;
    const int d    = c_dim[key];
    const int rows = 64 * d;
    const int foff = c_foff[key];
    const int tid = threadIdx.x;

    const float* xg;
    switch (key) {
        case 0: xg = x0; break; case 1: xg = x1; break;
        case 2: xg = x2; break; case 3: xg = x3; break;
        case 4: xg = x4; break; case 5: xg = x5; break;
        default: xg = x6; break;
    }
    xg += (size_t)(b * SSL + s0) * d * 64;

    {
        const float4* xg4 = (const float4*)xg;
        for (int i = tid; i < rows * 16; i += 256) {
            int r = i >> 4, k4 = (i & 15) * 4;
            float4 v = xg4[i];
            float* p = xs + r * XPITCH + k4;
            p[0]=tf32r(v.x); p[1]=tf32r(v.y); p[2]=tf32r(v.z); p[3]=tf32r(v.w);
        }
    }
    __syncthreads();

    const int wid  = tid >> 5;
    const int lane = tid & 31;
    const int gid  = lane >> 2;
    const int tig  = lane & 3;
    const int rbase = (wid & 3) * 16 * d;
    const int cbase = (wid >> 2) * 32;

    for (int m3 = 0; m3 < 3; m3++) {
        const float* wg = g_Wt + (key * 3 + m3) * 4096;

        float qacc[2][4][4];
        #pragma unroll
        for (int mf = 0; mf < 2; mf++)
            #pragma unroll
            for (int f = 0; f < 4; f++)
                #pragma unroll
                for (int c = 0; c < 4; c++) qacc[mf][f][c] = 0.0f;

        for (int k0 = 0; k0 < 64; k0 += 8) {
            uint32_t a[2][4];
            for (int mf = 0; mf < d; mf++) {
                const float* qb = xs + (rbase + mf * 16 + gid) * XPITCH + k0;
                a[mf][0] = __float_as_uint(qb[tig]);
                a[mf][1] = __float_as_uint(qb[8 * XPITCH + tig]);
                a[mf][2] = __float_as_uint(qb[tig + 4]);
                a[mf][3] = __float_as_uint(qb[8 * XPITCH + tig + 4]);
            }
            #pragma unroll
            for (int f = 0; f < 4; f++) {
                const float* kb = wg + (cbase + f * 8 + gid) * 64 + k0;
                uint32_t b0 = __float_as_uint(__ldg(kb + tig));
                uint32_t b1 = __float_as_uint(__ldg(kb + tig + 4));
                mma_tf32(qacc[0][f], a[0], b0, b1);
                if (d == 2) mma_tf32(qacc[1][f], a[1], b0, b1);
            }
        }

        float* dst = (m3 == 0) ? g_Q : (m3 == 1) ? g_K : g_V;
        for (int mf = 0; mf < d; mf++) {
            int rlo = rbase + mf * 16 + gid;
            int rhi = rlo + 8;
            int sslo = rlo / d, ddlo = rlo - sslo * d;
            int sshi = rhi / d, ddhi = rhi - sshi * d;
            #pragma unroll
            for (int f = 0; f < 4; f++) {
                int col = cbase + f * 8;
                int h = col >> 3;
                float* plo = dst + (((size_t)(b * HH + h)) * SSL + s0 + sslo) * DDIM
                                 + foff + ddlo * 8 + tig * 2;
                float* phi = dst + (((size_t)(b * HH + h)) * SSL + s0 + sshi) * DDIM
                                 + foff + ddhi * 8 + tig * 2;
                plo[0] = tf32r(qacc[mf][f][0]); plo[1] = tf32r(qacc[mf][f][1]);
                phi[0] = tf32r(qacc[mf][f][2]); phi[1] = tf32r(qacc[mf][f][3]);
            }
        }
    }
}

// ---------------------------------------------------------------------------
// Kernel 2: flash attention, FULL-ROW WARPS (exact R16)
// ---------------------------------------------------------------------------
#define QT 128
#define KT 64
#define NTILES (SSL / KT)
#define QPITCH 100
#define KPITCH 100
#define VPITCH 104

#define ATTN_SMEM_FLOATS (QT*QPITCH + KT*KPITCH + KT*VPITCH)

__global__ __launch_bounds__(256, 2) void k_attn()
{
    extern __shared__ float sm[];
    float* Qs = sm;                     // [128][100]
    float* Ks = Qs + QT * QPITCH;       // [64][100]
    float* Vs = Ks + KT * KPITCH;       // [64][104]

    const int bh = blockIdx.y;
    const int q0 = blockIdx.x * QT;
    const float* Qg = g_Q + ((size_t)bh * SSL + q0) * DDIM;
    const float* Kg = g_K + (size_t)bh * SSL * DDIM;
    const float* Vg = g_V + (size_t)bh * SSL * DDIM;

    const int tid  = threadIdx.x;
    const int wid  = tid >> 5;
    const int lane = tid & 31;
    const int gid  = lane >> 2;
    const int tig  = lane & 3;
    const int wbase = wid * 16;
    const float scale = 0.1020620726159658f;   // 1/sqrt(96)

    const int midx = lane >> 3, mrow = lane & 7;
    const uint32_t qaddr =
        s2u(&Qs[(wbase + (midx & 1) * 8 + mrow) * QPITCH + (midx >> 1) * 4]);
    const uint32_t kaddr =
        s2u(&Ks[((midx >> 1) * 8 + mrow) * KPITCH + (midx & 1) * 4]);

    for (int i = tid; i < QT * (DDIM / 4); i += 256) {
        int r = i / (DDIM / 4), c4 = (i - r * (DDIM / 4)) * 4;
        *(float4*)&Qs[r * QPITCH + c4] = *(const float4*)(Qg + r * DDIM + c4);
    }

    float oacc[12][4];
    #pragma unroll
    for (int nf = 0; nf < 12; nf++)
        #pragma unroll
        for (int c = 0; c < 4; c++) oacc[nf][c] = 0.0f;

    float lsum0 = 0.0f, lsum1 = 0.0f;

    const int srcA = (lane & ~3) | (tig >> 1);
    const int srcB = srcA + 2;
    const bool oddt = (tig & 1) != 0;

    for (int t = 0; t < NTILES; t++) {
        __syncthreads();

        {
            const float* Kt = Kg + (size_t)t * KT * DDIM;
            const float* Vt = Vg + (size_t)t * KT * DDIM;
            for (int i = tid; i < KT * (DDIM / 4); i += 256) {
                int r = i / (DDIM / 4), c4 = (i - r * (DDIM / 4)) * 4;
                cp_async16(s2u(Ks + r * KPITCH + c4), Kt + (size_t)r * DDIM + c4);
                cp_async16(s2u(Vs + r * VPITCH + c4), Vt + (size_t)r * DDIM + c4);
            }
            CP_COMMIT();
            asm volatile("cp.async.wait_group 0;");
        }
        __syncthreads();

        float qacc[8][4];
        #pragma unroll
        for (int f = 0; f < 8; f++)
            #pragma unroll
            for (int c = 0; c < 4; c++) qacc[f][c] = 0.0f;

        #pragma unroll
        for (int ks = 0; ks < DDIM / 8; ks++) {
            const int k0 = ks * 8;
            uint32_t a[4];
            ldsm_x4(a[0], a[1], a[2], a[3], qaddr + k0 * 4);
            #pragma unroll
            for (int np = 0; np < 4; np++) {
                uint32_t b0, b1, b2, b3;
                ldsm_x4(b0, b1, b2, b3,
                        kaddr + (uint32_t)(np * 16 * KPITCH + k0) * 4);
                mma_tf32(qacc[2 * np],     a, b0, b1);
                mma_tf32(qacc[2 * np + 1], a, b2, b3);
            }
        }

        #pragma unroll
        for (int f = 0; f < 8; f++) {
            float e0 = __expf(qacc[f][0] * scale);
            float e1 = __expf(qacc[f][1] * scale);
            float e2 = __expf(qacc[f][2] * scale);
            float e3 = __expf(qacc[f][3] * scale);
            lsum0 += e0 + e1;
            lsum1 += e2 + e3;
            e0 = tf32r(e0); e1 = tf32r(e1); e2 = tf32r(e2); e3 = tf32r(e3);
            float a0s = __shfl_sync(0xffffffffu, e0, srcA);
            float a1s = __shfl_sync(0xffffffffu, e1, srcA);
            float a2s = __shfl_sync(0xffffffffu, e2, srcA);
            float a3s = __shfl_sync(0xffffffffu, e3, srcA);
            float b0s = __shfl_sync(0xffffffffu, e0, srcB);
            float b1s = __shfl_sync(0xffffffffu, e1, srcB);
            float b2s = __shfl_sync(0xffffffffu, e2, srcB);
            float b3s = __shfl_sync(0xffffffffu, e3, srcB);
            qacc[f][0] = oddt ? a1s : a0s;
            qacc[f][1] = oddt ? a3s : a2s;
            qacc[f][2] = oddt ? b1s : b0s;
            qacc[f][3] = oddt ? b3s : b2s;
        }

        #pragma unroll
        for (int ks = 0; ks < 8; ks++) {
            const int k0 = ks * 8;
            uint32_t a[4] = {
                __float_as_uint(qacc[ks][0]), __float_as_uint(qacc[ks][1]),
                __float_as_uint(qacc[ks][2]), __float_as_uint(qacc[ks][3])
            };
            #pragma unroll
            for (int nf = 0; nf < 12; nf++) {
                int n = nf * 8 + gid;
                uint32_t b0 = __float_as_uint(Vs[(k0 + tig) * VPITCH + n]);
                uint32_t b1 = __float_as_uint(Vs[(k0 + tig + 4) * VPITCH + n]);
                mma_tf32(oacc[nf], a, b0, b1);
            }
        }
    }

    lsum0 += __shfl_xor_sync(0xffffffffu, lsum0, 1);
    lsum0 += __shfl_xor_sync(0xffffffffu, lsum0, 2);
    lsum1 += __shfl_xor_sync(0xffffffffu, lsum1, 1);
    lsum1 += __shfl_xor_sync(0xffffffffu, lsum1, 2);
    const float i0 = 1.0f / lsum0;
    const float i1 = 1.0f / lsum1;

    {
        float* plo = g_O + ((size_t)bh * SSL + q0 + wbase + gid) * DDIM;
        float* phi = g_O + ((size_t)bh * SSL + q0 + wbase + gid + 8) * DDIM;
        #pragma unroll
        for (int nf = 0; nf < 12; nf++) {
            int col = nf * 8 + tig * 2;
            plo[col]     = oacc[nf][0] * i0;
            plo[col + 1] = oacc[nf][1] * i0;
            phi[col]     = oacc[nf][2] * i1;
            phi[col + 1] = oacc[nf][3] * i1;
        }
    }
}

// ---------------------------------------------------------------------------
// Kernel 3: combine heads + per-key Wo projection, tf32 MMA (exact R12)
// ---------------------------------------------------------------------------
#define WPITCH 68
#define OUT_SMEM_FLOATS (64 * WPITCH + 128 * XPITCH)

__global__ __launch_bounds__(256) void k_out(
    const float* __restrict__ Wo, float* __restrict__ out)
{
    extern __shared__ float sm[];
    float* Ws = sm;                 // [64][68]  Wo native [o][k]
    float* xs = sm + 64 * WPITCH;   // [rows][68] combined heads

    const int key = blockIdx.z;
    const int b   = blockIdx.y;
    const int s0  = blockIdx.x * 64;
    const int d    = c_dim[key];
    const int rows = 64 * d;
    const int foff = c_foff[key];
    const int roff = c_roff[key];
    const int tid = threadIdx.x;

    const float* w = Wo + key * 4096;
    for (int i = tid; i < 4096; i += 256) {
        int o = i >> 6, k = i & 63;
        Ws[o * WPITCH + k] = tf32r(w[i]);
    }
    for (int i = tid; i < rows * 64; i += 256) {
        int row = i >> 6, mp = i & 63;
        int ss = row / d, dd = row - ss * d;
        xs[row * XPITCH + mp] = tf32r(
            g_O[(((size_t)(b * HH + (mp >> 3))) * SSL + s0 + ss) * DDIM
                + foff + dd * 8 + (mp & 7)]);
    }
    __syncthreads();

    const int wid  = tid >> 5;
    const int lane = tid & 31;
    const int gid  = lane >> 2;
    const int tig  = lane & 3;
    const int rbase = (wid & 3) * 16 * d;
    const int cbase = (wid >> 2) * 32;

    float qacc[2][4][4];
    #pragma unroll
    for (int mf = 0; mf < 2; mf++)
        #pragma unroll
        for (int f = 0; f < 4; f++)
            #pragma unroll
            for (int c = 0; c < 4; c++) qacc[mf][f][c] = 0.0f;

    for (int k0 = 0; k0 < 64; k0 += 8) {
        uint32_t a[2][4];
        for (int mf = 0; mf < d; mf++) {
            const float* qb = xs + (rbase + mf * 16 + gid) * XPITCH + k0;
            a[mf][0] = __float_as_uint(qb[tig]);
            a[mf][1] = __float_as_uint(qb[8 * XPITCH + tig]);
            a[mf][2] = __float_as_uint(qb[tig + 4]);
            a[mf][3] = __float_as_uint(qb[8 * XPITCH + tig + 4]);
        }
        #pragma unroll
        for (int f = 0; f < 4; f++) {
            const float* kb = Ws + (cbase + f * 8 + gid) * WPITCH + k0;
            uint32_t b0 = __float_as_uint(kb[tig]);
            uint32_t b1 = __float_as_uint(kb[tig + 4]);
            mma_tf32(qacc[0][f], a[0], b0, b1);
            if (d == 2) mma_tf32(qacc[1][f], a[1], b0, b1);
        }
    }

    for (int mf = 0; mf < d; mf++) {
        int rlo = rbase + mf * 16 + gid;
        int rhi = rlo + 8;
        int sslo = rlo / d, ddlo = rlo - sslo * d;
        int sshi = rhi / d, ddhi = rhi - sshi * d;
        #pragma unroll
        for (int f = 0; f < 4; f++) {
            int col = cbase + f * 8 + tig * 2;
            float* plo = out + (((size_t)(b * SSL) + s0 + sslo) * 12 + roff + ddlo) * 64 + col;
            float* phi = out + (((size_t)(b * SSL) + s0 + sshi) * 12 + roff + ddhi) * 64 + col;
            plo[0] = qacc[mf][f][0]; plo[1] = qacc[mf][f][1];
            phi[0] = qacc[mf][f][2]; phi[1] = qacc[mf][f][3];
        }
    }
}

// ---------------------------------------------------------------------------
extern "C" void kernel_launch(void* const* d_in, const int* in_sizes, int n_in,
                              void* d_out, int out_size)
{
    const float* x0 = (const float*)d_in[0];
    const float* x1 = (const float*)d_in[1];
    const float* x2 = (const float*)d_in[2];
    const float* x3 = (const float*)d_in[3];
    const float* x4 = (const float*)d_in[4];
    const float* x5 = (const float*)d_in[5];
    const float* x6 = (const float*)d_in[6];
    const float* Wq = (const float*)d_in[7];
    const float* Wk = (const float*)d_in[8];
    const float* Wv = (const float*)d_in[9];
    const float* Wo = (const float*)d_in[10];
    float* out = (float*)d_out;

    const int proj_smem = PROJ_SMEM_FLOATS * 4;            // ~35 KB -> 4 blocks/SM
    const int attn_smem = ATTN_SMEM_FLOATS * 4;            // ~103 KB -> 2 blocks/SM
    const int out_smem  = OUT_SMEM_FLOATS * 4;             // ~52 KB

    cudaFuncSetAttribute(k_proj, cudaFuncAttributeMaxDynamicSharedMemorySize, proj_smem);
    cudaFuncSetAttribute(k_attn, cudaFuncAttributeMaxDynamicSharedMemorySize, attn_smem);
    cudaFuncSetAttribute(k_out,  cudaFuncAttributeMaxDynamicSharedMemorySize, out_smem);

    k_prew<<<21, 256>>>(Wq, Wk, Wv);
    k_proj<<<dim3(SSL / 64, BB, NKEY), 256, proj_smem>>>(
        x0, x1, x2, x3, x4, x5, x6);
    k_attn<<<dim3(SSL / QT, BB * HH), 256, attn_smem>>>();
    k_out<<<dim3(SSL / 64, BB, NKEY), 256, out_smem>>>(Wo, out);
}